// round 17
// baseline (speedup 1.0000x reference)
#include <cuda_runtime.h>
#include <cuda_fp16.h>
#include <cstdint>
#include <cstddef>
#include <cstring>

constexpr int Bn  = 512;
constexpr int QLn = 128;
constexpr int ALn = 512;
constexpr int Fn  = 400;
constexpr int Fp  = 512;
constexpr int EPW = 304;                 // e padded to 19*16 (emb row stride, halves)
constexpr int NS  = 19;
constexpr int NEMBP = 50001 * EPW;
constexpr int NBUF = 5;
constexpr int STAGE = (384 + 132) * 32;  // 16512 B
constexpr int SMEM_ALL = NBUF * STAGE;   // 82560
constexpr int SMEM_PW2 = 400 * 39 * 4;   // 62400

// ---------------- device scratch ----------------
__device__ __align__(256) float d_biasPad[Fp];
__device__ __align__(256) float d_b2[Fp];
__device__ __align__(256) __half d_W16[3 * Fp * EPW];    // fp16 conv_w [j][f][e]
__device__ __align__(256) __half d_W216[3 * Fp * EPW];   // fp16 U^T conv_w
__device__ __align__(256) __half d_emb16[NEMBP];         // fp16 padded emb
__device__ __align__(256) float d_A[(size_t)Bn * Fn * ALn];
__device__ __align__(256) float d_Q[(size_t)Bn * Fn * QLn];
__device__ __align__(256) float d_tQ[(size_t)Bn * Fn * QLn];
__device__ __align__(256) float d_maxQp[Bn * 4 * QLn];
__device__ __align__(256) float d_maxA[Bn * ALn];

// ---------------- helpers ----------------
__device__ __forceinline__ float tanh_fast(float x) {
    float e = __expf(2.0f * x);
    return 1.0f - __fdividef(2.0f, e + 1.0f);
}
__device__ __forceinline__ uint32_t smem_u32(const void* p) {
    uint32_t a;
    asm("{ .reg .u64 t; cvta.to.shared.u64 t, %1; cvt.u32.u64 %0, t; }" : "=r"(a) : "l"(p));
    return a;
}
__device__ __forceinline__ uint32_t packh2(float v0, float v1) {
    __half2 h = __floats2half2_rn(v0, v1);
    uint32_t w;
    memcpy(&w, &h, 4);
    return w;
}
__device__ __forceinline__ void mma_f16(float* c, const uint32_t* a, uint32_t b0, uint32_t b1) {
    asm volatile(
        "mma.sync.aligned.m16n8k16.row.col.f32.f16.f16.f32 "
        "{%0,%1,%2,%3}, {%4,%5,%6,%7}, {%8,%9}, {%0,%1,%2,%3};"
        : "+f"(c[0]), "+f"(c[1]), "+f"(c[2]), "+f"(c[3])
        : "r"(a[0]), "r"(a[1]), "r"(a[2]), "r"(a[3]), "r"(b0), "r"(b1));
}
__device__ __forceinline__ void ldsm4(uint32_t* r, uint32_t addr) {
    asm volatile("ldmatrix.sync.aligned.m8n8.x4.shared.b16 {%0,%1,%2,%3}, [%4];"
        : "=r"(r[0]), "=r"(r[1]), "=r"(r[2]), "=r"(r[3]) : "r"(addr));
}
__device__ __forceinline__ void cp16(uint32_t dst, const void* src, uint32_t sz) {
    asm volatile("cp.async.cg.shared.global [%0], [%1], 16, %2;"
        :: "r"(dst), "l"(src), "r"(sz) : "memory");
}
__device__ __forceinline__ void sts128(uint32_t addr, uint32_t w0, uint32_t w1,
                                       uint32_t w2, uint32_t w3) {
    asm volatile("st.shared.v4.b32 [%0], {%1,%2,%3,%4};"
        :: "r"(addr), "r"(w0), "r"(w1), "r"(w2), "r"(w3));
}
// row-major tiles of 32B rows (2x16B chunks), chunk XOR swizzle
__device__ __forceinline__ uint32_t swaddr(uint32_t base, uint32_t row, uint32_t chunk) {
    return base + row * 32u + ((chunk ^ ((row >> 2) & 1u)) << 4);
}

// ---------------- prep kernels ----------------
// W16 fill + biasPad + b2 (= U^T conv_b)
__global__ void prep_w(const float* __restrict__ cw, const float* __restrict__ cb,
                       const float* __restrict__ U,
                       float* __restrict__ biasPad, float* __restrict__ b2,
                       __half* __restrict__ W16) {
    int idx = blockIdx.x * 256 + threadIdx.x;
    if (idx < Fp) {
        biasPad[idx] = (idx < Fn) ? cb[idx] : 0.0f;
        float a = 0.0f;
        if (idx < Fn) for (int f = 0; f < Fn; f++) a += U[f * Fn + idx] * cb[f];
        b2[idx] = a;
    }
    if (idx >= 3 * Fp * EPW) return;
    int j = idx / (Fp * EPW), rem = idx - j * (Fp * EPW);
    int f = rem / EPW, e = rem - f * EPW;
    float v = 0.0f;
    if (f < Fn && e < 300) v = cw[(f * 300 + e) * 3 + j];
    W16[idx] = __float2half_rn(v);
}

// Tiled W2 = U^T conv_w: grid (3, 8 e-tiles of 38, 4 g-tiles of 128), block 256.
__global__ void __launch_bounds__(256)
prep_w2t(const float* __restrict__ U, const float* __restrict__ cw,
         __half* __restrict__ W216) {
    extern __shared__ float scw[];   // [400][39]
    const int j = blockIdx.x, et = blockIdx.y, gt = blockIdx.z;
    const int e0 = et * 38;
    const int t = threadIdx.x;

    for (int i = t; i < 400 * 38; i += 256) {
        int f = i / 38, e = i - f * 38;
        int ee = e0 + e;
        scw[f * 39 + e] = (ee < 300) ? cw[(f * 300 + ee) * 3 + j] : 0.0f;
    }
    __syncthreads();

    const int g = gt * 128 + (t & 127);
    const int eh = (t >> 7) * 19;
    float acc[19];
#pragma unroll
    for (int i = 0; i < 19; i++) acc[i] = 0.0f;
    for (int f = 0; f < Fn; f++) {
        float u = (g < Fn) ? U[f * Fn + g] : 0.0f;
        const float* row = scw + f * 39 + eh;
#pragma unroll
        for (int i = 0; i < 19; i++) acc[i] += u * row[i];
    }
    __half* dst = W216 + (size_t)j * Fp * EPW + (size_t)g * EPW + e0 + eh;
#pragma unroll
    for (int i = 0; i < 19; i++) dst[i] = __float2half_rn(acc[i]);
}

__global__ void emb_cvt(const float* __restrict__ emb, __half* __restrict__ e16) {
    int idx = blockIdx.x * 256 + threadIdx.x;
    if (idx >= NEMBP) return;
    int t = idx / EPW, e = idx - t * EPW;
    float v = (e < 300) ? emb[(size_t)t * 300 + e] : 0.0f;
    e16[idx] = __float2half_rn(v);
}

// ---------------- fill pieces (256 threads), k-chunk = 16 halves/row ----------------
__device__ __forceinline__ void fill_w(
    uint32_t stage, int e0, int tid, int fBase, const __half* __restrict__ W) {
#pragma unroll
    for (int it = 0; it < 3; it++) {
        int idx = it * 256 + tid;
        uint32_t row = (uint32_t)idx >> 1, chunk = idx & 1;
        uint32_t j = row >> 7, f = row & 127u;
        const __half* src = W + ((size_t)j * Fp + fBase + f) * EPW + e0 + chunk * 8;
        cp16(swaddr(stage, row, chunk), src, (fBase + (int)f < Fn) ? 16u : 0u);
    }
}

__device__ __forceinline__ void fill_x(
    uint32_t stage, int e0, int tid,
    const __half* __restrict__ e16, const int* stok) {
#pragma unroll
    for (int it = 0; it < 2; it++) {
        int idx = it * 256 + tid;
        if (idx < 264) {
            uint32_t r = (uint32_t)idx >> 1, chunk = idx & 1;
            int t = stok[r];
            const __half* src = e16 + (size_t)(t < 0 ? 0 : t) * EPW + e0 + chunk * 8;
            cp16(swaddr(stage, 384u + r, chunk), src, (t < 0) ? 0u : 16u);
        }
    }
}

// ---------------- 32f x 64l warp compute stage ----------------
__device__ __forceinline__ void conv_cs32(
    uint32_t stg, int lane, uint32_t wRowBase, uint32_t xRowBase,
    float acc[2][8][4]) {
    const uint32_t frA = (((uint32_t)lane >> 3) & 1u) * 8u + ((uint32_t)lane & 7u);
    const uint32_t chA = (uint32_t)lane >> 4;
    const uint32_t frB = (((uint32_t)lane >> 4) << 3) + ((uint32_t)lane & 7u);
    const uint32_t chB = ((uint32_t)lane >> 3) & 1u;
#pragma unroll
    for (int j = 0; j < 3; j++) {
        uint32_t a[2][4], bq[16];
#pragma unroll
        for (int mt = 0; mt < 2; mt++) {
            uint32_t rowA = wRowBase + (uint32_t)(j * 128 + mt * 16) + frA;
            ldsm4(a[mt], swaddr(stg, rowA, chA));
        }
#pragma unroll
        for (int p = 0; p < 4; p++) {
            uint32_t rowB = xRowBase + (uint32_t)(p * 16) + frB + (uint32_t)j;
            ldsm4(bq + 4 * p, swaddr(stg, rowB, chB));
        }
#pragma unroll
        for (int mt = 0; mt < 2; mt++)
#pragma unroll
            for (int nt = 0; nt < 8; nt++)
                mma_f16(acc[mt][nt], a[mt], bq[2 * nt], bq[2 * nt + 1]);
    }
}

// ---------------- unified conv kernel ----------------
// grid (6, 4, 512): x<4 -> A-conv l-tile; x=4 -> Q; x=5 -> tQ. Tile 128f x 128l.
__global__ void __launch_bounds__(256, 2)
conv_all(const int* __restrict__ question, const int* __restrict__ answer,
         const __half* __restrict__ e16,
         const __half* __restrict__ W1, const __half* __restrict__ W2,
         const float* __restrict__ bias1, const float* __restrict__ bias2,
         float* __restrict__ Ao, float* __restrict__ Qo, float* __restrict__ tQo) {
    extern __shared__ uint32_t dsm[];
    __shared__ int stok[132];

    const int tid = threadIdx.x;
    const int wid = tid >> 5, lane = tid & 31;
    const int wmf = wid & 3, wnf = wid >> 2;
    const int fBase = blockIdx.y * 128;
    const int b = blockIdx.z;
    const uint32_t sbase = smem_u32(dsm);
    const bool fvalid = (fBase + wmf * 32) < Fn;

    const int xi = blockIdx.x;
    const int* tok;
    int L, lBase;
    const __half* W;
    const float* bias;
    float* out;
    if (xi < 4) {
        tok = answer;  L = ALn;  lBase = xi * 128;
        W = W1;  bias = bias1;  out = Ao;
    } else if (xi == 4) {
        tok = question;  L = QLn;  lBase = 0;
        W = W1;  bias = bias1;  out = Qo;
    } else {
        tok = question;  L = QLn;  lBase = 0;
        W = W2;  bias = bias2;  out = tQo;
    }

    if (tid < 132) {
        int pos = lBase + tid - 1;
        stok[tid] = (pos >= 0 && pos < L && tid < 130) ? tok[b * L + pos] : -1;
    }
    __syncthreads();

    float acc[2][8][4];
#pragma unroll
    for (int mt = 0; mt < 2; mt++)
#pragma unroll
        for (int nt = 0; nt < 8; nt++)
#pragma unroll
            for (int i = 0; i < 4; i++) acc[mt][nt][i] = 0.0f;

#pragma unroll
    for (int p = 0; p < 4; p++) {
        uint32_t stg = sbase + (uint32_t)p * STAGE;
        fill_w(stg, p * 16, tid, fBase, W);
        fill_x(stg, p * 16, tid, e16, stok);
        asm volatile("cp.async.commit_group;" ::: "memory");
    }
    for (int s = 0; s < NS; s++) {
        asm volatile("cp.async.wait_group 3;" ::: "memory");
        __syncthreads();
        if (s + 4 < NS) {
            uint32_t stg2 = sbase + (uint32_t)((s + 4) % NBUF) * STAGE;
            fill_w(stg2, (s + 4) * 16, tid, fBase, W);
            fill_x(stg2, (s + 4) * 16, tid, e16, stok);
        }
        asm volatile("cp.async.commit_group;" ::: "memory");
        const uint32_t stg = sbase + (uint32_t)(s % NBUF) * STAGE;
        if (fvalid)
            conv_cs32(stg, lane, (uint32_t)(wmf * 32), 384u + (uint32_t)(wnf * 64), acc);
    }

    if (fvalid) {
        const int r4 = lane & 3, q = lane >> 2;
#pragma unroll
        for (int mt = 0; mt < 2; mt++) {
            int f0 = fBase + wmf * 32 + mt * 16 + q;
            float bv0 = (f0 < Fn) ? bias[f0] : 0.0f;
            float bv1 = (f0 + 8 < Fn) ? bias[f0 + 8] : 0.0f;
#pragma unroll
            for (int nt = 0; nt < 8; nt++) {
                int l = lBase + wnf * 64 + nt * 8 + r4 * 2;
                if (f0 < Fn) {
                    float2 v = make_float2(acc[mt][nt][0] + bv0, acc[mt][nt][1] + bv0);
                    *(float2*)(out + ((size_t)b * Fn + f0) * L + l) = v;
                }
                if (f0 + 8 < Fn) {
                    float2 v = make_float2(acc[mt][nt][2] + bv1, acc[mt][nt][3] + bv1);
                    *(float2*)(out + ((size_t)b * Fn + f0 + 8) * L + l) = v;
                }
            }
        }
    }
}

// ---------------- fp16 G-tile kernel (ping-pong staging) ----------------
__global__ void __launch_bounds__(256)
g_mma(const float* __restrict__ tQ, const float* __restrict__ A,
      float* __restrict__ maxQp, float* __restrict__ maxA) {
    __shared__ __align__(16) uint32_t stg[4096];  // 2 x 8 KB
    __shared__ float sRow[2][128];
    __shared__ float sCol[4][128];

    const int tid = threadIdx.x;
    const int wid = tid >> 5, lane = tid & 31;
    const int wmf = wid & 3, wnf = wid >> 2;
    const int r4 = lane & 3, q8 = lane >> 2;
    const int at = blockIdx.x, b = blockIdx.y;

    const float* tqb = tQ + (size_t)b * Fn * QLn;
    const float* ab  = A  + (size_t)b * Fn * ALn + at * 128;
    const int role = tid >> 7;
    const int rrow = tid & 127;
    const float* src = role ? (ab + rrow) : (tqb + rrow);
    const int sstr = role ? ALn : QLn;
    const uint32_t sb = smem_u32(stg);

    const uint32_t frA = (((uint32_t)lane >> 3) & 1u) * 8u + ((uint32_t)lane & 7u);
    const uint32_t chA = (uint32_t)lane >> 4;
    const uint32_t frB = (((uint32_t)lane >> 4) << 3) + ((uint32_t)lane & 7u);
    const uint32_t chB = ((uint32_t)lane >> 3) & 1u;
    const uint32_t rowS = (uint32_t)(role * 128 + rrow);

    float acc[2][8][4];
#pragma unroll
    for (int mt = 0; mt < 2; mt++)
#pragma unroll
        for (int nt = 0; nt < 8; nt++)
#pragma unroll
            for (int i = 0; i < 4; i++) acc[mt][nt][i] = 0.0f;

    float v[16];
#pragma unroll
    for (int i = 0; i < 16; i++) v[i] = src[(size_t)i * sstr];
    {
        uint32_t w[8];
#pragma unroll
        for (int c = 0; c < 8; c++) w[c] = packh2(v[2 * c], v[2 * c + 1]);
        sts128(swaddr(sb, rowS, 0), w[0], w[1], w[2], w[3]);
        sts128(swaddr(sb, rowS, 1), w[4], w[5], w[6], w[7]);
    }
    __syncthreads();

    for (int s = 0; s < 25; s++) {
        const uint32_t sbc = sb + (uint32_t)(s & 1) * 8192u;
        const uint32_t sbn = sb + (uint32_t)((s + 1) & 1) * 8192u;
        if (s < 24) {
            const float* s2 = src + (size_t)(s + 1) * 16 * sstr;
#pragma unroll
            for (int i = 0; i < 16; i++) v[i] = s2[(size_t)i * sstr];
        }
        // compute stage s from sbc
        uint32_t a[2][4], bq[16];
#pragma unroll
        for (int mt = 0; mt < 2; mt++) {
            uint32_t rowA = (uint32_t)(wmf * 32 + mt * 16) + frA;
            ldsm4(a[mt], swaddr(sbc, rowA, chA));
        }
#pragma unroll
        for (int p = 0; p < 4; p++) {
            uint32_t rowB = 128u + (uint32_t)(wnf * 64 + p * 16) + frB;
            ldsm4(bq + 4 * p, swaddr(sbc, rowB, chB));
        }
#pragma unroll
        for (int nt = 0; nt < 8; nt++) {
            mma_f16(acc[0][nt], a[0], bq[2 * nt], bq[2 * nt + 1]);
            mma_f16(acc[1][nt], a[1], bq[2 * nt], bq[2 * nt + 1]);
        }
        // stage s+1 into the other buffer
        if (s < 24) {
            uint32_t w[8];
#pragma unroll
            for (int c = 0; c < 8; c++) w[c] = packh2(v[2 * c], v[2 * c + 1]);
            sts128(swaddr(sbn, rowS, 0), w[0], w[1], w[2], w[3]);
            sts128(swaddr(sbn, rowS, 1), w[4], w[5], w[6], w[7]);
        }
        __syncthreads();
    }

#pragma unroll
    for (int mt = 0; mt < 2; mt++)
#pragma unroll
        for (int nt = 0; nt < 8; nt++)
#pragma unroll
            for (int ci = 0; ci < 4; ci++)
                acc[mt][nt][ci] = tanh_fast(acc[mt][nt][ci]);

    float rm[4] = {-2.f, -2.f, -2.f, -2.f};
    float cm[16];
#pragma unroll
    for (int i = 0; i < 16; i++) cm[i] = -2.f;
#pragma unroll
    for (int mt = 0; mt < 2; mt++)
#pragma unroll
        for (int nt = 0; nt < 8; nt++)
#pragma unroll
            for (int ci = 0; ci < 4; ci++) {
                float g = acc[mt][nt][ci];
                rm[mt * 2 + (ci >> 1)] = fmaxf(rm[mt * 2 + (ci >> 1)], g);
                cm[nt * 2 + (ci & 1)] = fmaxf(cm[nt * 2 + (ci & 1)], g);
            }
#pragma unroll
    for (int k = 0; k < 4; k++) {
        rm[k] = fmaxf(rm[k], __shfl_xor_sync(0xffffffffu, rm[k], 1));
        rm[k] = fmaxf(rm[k], __shfl_xor_sync(0xffffffffu, rm[k], 2));
    }
#pragma unroll
    for (int k = 0; k < 16; k++) {
        cm[k] = fmaxf(cm[k], __shfl_xor_sync(0xffffffffu, cm[k], 4));
        cm[k] = fmaxf(cm[k], __shfl_xor_sync(0xffffffffu, cm[k], 8));
        cm[k] = fmaxf(cm[k], __shfl_xor_sync(0xffffffffu, cm[k], 16));
    }
    if (r4 == 0) {
#pragma unroll
        for (int mt = 0; mt < 2; mt++)
#pragma unroll
            for (int h = 0; h < 2; h++)
                sRow[wnf][wmf * 32 + mt * 16 + h * 8 + q8] = rm[mt * 2 + h];
    }
    if (q8 == 0) {
#pragma unroll
        for (int nt = 0; nt < 8; nt++)
#pragma unroll
            for (int c = 0; c < 2; c++)
                sCol[wmf][wnf * 64 + nt * 8 + r4 * 2 + c] = cm[nt * 2 + c];
    }
    __syncthreads();
    if (tid < 128) {
        maxQp[((size_t)b * 4 + at) * QLn + tid] = fmaxf(sRow[0][tid], sRow[1][tid]);
        float m = fmaxf(fmaxf(sCol[0][tid], sCol[1][tid]), fmaxf(sCol[2][tid], sCol[3][tid]));
        maxA[(size_t)b * ALn + at * 128 + tid] = m;
    }
}

// ---------------- finalize ----------------
__device__ __forceinline__ float blkReduce(float v, bool domax) {
    __shared__ float sb[8];
#pragma unroll
    for (int o = 16; o; o >>= 1) {
        float ov = __shfl_xor_sync(0xffffffffu, v, o);
        v = domax ? fmaxf(v, ov) : v + ov;
    }
    __syncthreads();
    if ((threadIdx.x & 31) == 0) sb[threadIdx.x >> 5] = v;
    __syncthreads();
    float r = sb[0];
#pragma unroll
    for (int w = 1; w < 8; w++) r = domax ? fmaxf(r, sb[w]) : r + sb[w];
    return r;
}

__global__ void __launch_bounds__(256)
final_kernel(const float* __restrict__ Q, const float* __restrict__ A,
             const float* __restrict__ maxQp, const float* __restrict__ maxA,
             float* __restrict__ out) {
    __shared__ float roQ[QLn];
    __shared__ float roA[ALn];
    __shared__ float rQ[Fn];
    __shared__ float rA[Fn];
    const int b = blockIdx.x, tid = threadIdx.x;

    float v = -2.0f;
    if (tid < QLn) {
        const float* mp = maxQp + (size_t)b * 4 * QLn + tid;
        v = fmaxf(fmaxf(mp[0], mp[QLn]), fmaxf(mp[2 * QLn], mp[3 * QLn]));
    }
    float m = blkReduce(v, true);
    float e = (tid < QLn) ? __expf(v - m) : 0.0f;
    float s = blkReduce(e, false);
    if (tid < QLn) roQ[tid] = e / s;

    float v0 = maxA[(size_t)b * ALn + tid];
    float v1 = maxA[(size_t)b * ALn + 256 + tid];
    m = blkReduce(fmaxf(v0, v1), true);
    float e0 = __expf(v0 - m), e1 = __expf(v1 - m);
    s = blkReduce(e0 + e1, false);
    roA[tid] = e0 / s;
    roA[tid + 256] = e1 / s;
    __syncthreads();

    for (int f = tid; f < Fn; f += 256) {
        const float4* qr = (const float4*)(Q + ((size_t)b * Fn + f) * QLn);
        float a = 0.0f;
#pragma unroll 8
        for (int c = 0; c < QLn / 4; c++) {
            float4 qv = qr[c];
            const float* w = &roQ[c * 4];
            a += qv.x * w[0] + qv.y * w[1] + qv.z * w[2] + qv.w * w[3];
        }
        rQ[f] = a;
    }
    for (int f = tid; f < Fn; f += 256) {
        const float4* ar = (const float4*)(A + ((size_t)b * Fn + f) * ALn);
        float a = 0.0f;
#pragma unroll 8
        for (int c = 0; c < ALn / 4; c++) {
            float4 qv = ar[c];
            const float* w = &roA[c * 4];
            a += qv.x * w[0] + qv.y * w[1] + qv.z * w[2] + qv.w * w[3];
        }
        rA[f] = a;
    }
    __syncthreads();

    float d = 0.0f, qq = 0.0f, aa = 0.0f;
    for (int f = tid; f < Fn; f += 256) {
        float x = rQ[f], y = rA[f];
        d += x * y; qq += x * x; aa += y * y;
    }
    d = blkReduce(d, false);
    qq = blkReduce(qq, false);
    aa = blkReduce(aa, false);
    if (tid == 0)
        out[b] = d / (fmaxf(sqrtf(qq), 1e-8f) * fmaxf(sqrtf(aa), 1e-8f));
}

// ---------------- launch ----------------
extern "C" void kernel_launch(void* const* d_in, const int* in_sizes, int n_in,
                              void* d_out, int out_size) {
    const int*   question = (const int*)d_in[0];
    const int*   answer   = (const int*)d_in[1];
    const float* emb      = (const float*)d_in[2];
    const float* conv_w   = (const float*)d_in[3];
    const float* conv_b   = (const float*)d_in[4];
    const float* U        = (const float*)d_in[5];
    float* out = (float*)d_out;

    float *biasPad, *b2, *Ac, *Qc, *tQc, *maxQp, *maxA;
    __half *W16, *W216, *e16;
    cudaGetSymbolAddress((void**)&biasPad, d_biasPad);
    cudaGetSymbolAddress((void**)&b2,      d_b2);
    cudaGetSymbolAddress((void**)&W16,     d_W16);
    cudaGetSymbolAddress((void**)&W216,    d_W216);
    cudaGetSymbolAddress((void**)&e16,     d_emb16);
    cudaGetSymbolAddress((void**)&Ac,      d_A);
    cudaGetSymbolAddress((void**)&Qc,      d_Q);
    cudaGetSymbolAddress((void**)&tQc,     d_tQ);
    cudaGetSymbolAddress((void**)&maxQp,   d_maxQp);
    cudaGetSymbolAddress((void**)&maxA,    d_maxA);

    cudaFuncSetAttribute(conv_all, cudaFuncAttributeMaxDynamicSharedMemorySize, SMEM_ALL);
    cudaFuncSetAttribute(prep_w2t, cudaFuncAttributeMaxDynamicSharedMemorySize, SMEM_PW2);

    const int prepBlocks = (3 * Fp * EPW + 255) / 256;
    prep_w<<<prepBlocks, 256>>>(conv_w, conv_b, U, biasPad, b2, W16);
    dim3 gP(3, 8, 4);
    prep_w2t<<<gP, 256, SMEM_PW2>>>(U, conv_w, W216);
    emb_cvt<<<(NEMBP + 255) / 256, 256>>>(emb, e16);

    dim3 gC(6, Fp / 128, Bn);   // x: 0-3 = A-tiles; 4 = Q; 5 = tQ
    conv_all<<<gC, 256, SMEM_ALL>>>(question, answer, e16, W16, W216,
                                    biasPad, b2, Ac, Qc, tQc);

    dim3 gG(4, Bn);
    g_mma<<<gG, 256>>>(tQc, Ac, maxQp, maxA);
    final_kernel<<<Bn, 256>>>(Qc, Ac, maxQp, maxA, out);
}